// round 4
// baseline (speedup 1.0000x reference)
#include <cuda_runtime.h>

#define N_Q 1024
#define N_O 2048
#define LATENT 128
#define HEADS 4
#define SEGS 8
#define SEG_O (N_O / SEGS)          // 256
#define O_TILE 32
#define N_TILES (SEG_O / O_TILE)    // 8

typedef unsigned long long ull;

// ---------------- scratch (static device globals; no allocation) ----------------
__device__ float g_v[N_O * LATENT];                    // value vectors
__device__ float g_bo[N_O * LATENT];                   // per-obs linear term
__device__ float g_aq[N_Q * LATENT];                   // per-query linear term (incl b1)
__device__ float g_m2[SEGS * N_Q * HEADS];             // per-segment running max
__device__ float g_s2[SEGS * N_Q * HEADS];             // per-segment exp-sum
__device__ float g_acc[SEGS * N_Q * LATENT];           // per-segment weighted partials

// ---------------- packed f32x2 helpers ----------------
__device__ __forceinline__ ull fma2(ull a, ull b, ull c) {
    ull d; asm("fma.rn.f32x2 %0, %1, %2, %3;" : "=l"(d) : "l"(a), "l"(b), "l"(c)); return d;
}
__device__ __forceinline__ ull mul2(ull a, ull b) {
    ull d; asm("mul.rn.f32x2 %0, %1, %2;" : "=l"(d) : "l"(a), "l"(b)); return d;
}
__device__ __forceinline__ ull add2(ull a, ull b) {
    ull d; asm("add.rn.f32x2 %0, %1, %2;" : "=l"(d) : "l"(a), "l"(b)); return d;
}
__device__ __forceinline__ ull relu2(ull a) {
    ull d;
    asm("{\n\t"
        ".reg .f32 lo, hi;\n\t"
        "mov.b64 {lo, hi}, %1;\n\t"
        "max.f32 lo, lo, 0f00000000;\n\t"
        "max.f32 hi, hi, 0f00000000;\n\t"
        "mov.b64 %0, {lo, hi};\n\t"
        "}" : "=l"(d) : "l"(a));
    return d;
}
__device__ __forceinline__ ull pack2(float x, float y) {
    ull d; asm("mov.b64 %0, {%1, %2};" : "=l"(d) : "f"(x), "f"(y)); return d;
}
__device__ __forceinline__ float2 unpack2(ull a) {
    float2 f; asm("mov.b64 {%0, %1}, %2;" : "=f"(f.x), "=f"(f.y) : "l"(a)); return f;
}

// ---------------- kernel 1: per-obs precompute (LayerNorm -> v, and bo) ----------------
__global__ void pre_o_kernel(const float* __restrict__ h_obs,
                             const float* __restrict__ pos_obs,
                             const float* __restrict__ W1,
                             const float* __restrict__ ln_gamma,
                             const float* __restrict__ ln_beta,
                             const float* __restrict__ Wv,
                             const float* __restrict__ bv) {
    __shared__ float s_hn[16][LATENT];
    __shared__ float s_red[2][4];
    int l = threadIdx.x;
    int w = l >> 5, lane = l & 31;

    float bw0 = W1[(3 + 0) * LATENT + l] - W1[(6 + 0) * LATENT + l];
    float bw1 = W1[(3 + 1) * LATENT + l] - W1[(6 + 1) * LATENT + l];
    float bw2 = W1[(3 + 2) * LATENT + l] - W1[(6 + 2) * LATENT + l];
    float gam = ln_gamma[l], bet = ln_beta[l];

    for (int oi = 0; oi < 16; oi++) {
        int o = blockIdx.x * 16 + oi;
        float h = h_obs[o * LATENT + l];
        float s1 = h, s2 = h * h;
        #pragma unroll
        for (int off = 16; off; off >>= 1) {
            s1 += __shfl_xor_sync(0xffffffffu, s1, off);
            s2 += __shfl_xor_sync(0xffffffffu, s2, off);
        }
        if (lane == 0) { s_red[0][w] = s1; s_red[1][w] = s2; }
        __syncthreads();
        float S1 = s_red[0][0] + s_red[0][1] + s_red[0][2] + s_red[0][3];
        float S2 = s_red[1][0] + s_red[1][1] + s_red[1][2] + s_red[1][3];
        __syncthreads();
        float mu = S1 * (1.0f / LATENT);
        float var = S2 * (1.0f / LATENT) - mu * mu;
        float hn = (h - mu) * rsqrtf(var + 1e-5f) * gam + bet;
        s_hn[oi][l] = hn;
        float p0 = pos_obs[o * 3 + 0], p1 = pos_obs[o * 3 + 1], p2 = pos_obs[o * 3 + 2];
        g_bo[o * LATENT + l] = p0 * bw0 + p1 * bw1 + p2 * bw2;
    }
    __syncthreads();

    float acc[16];
    float b = bv[l];
    #pragma unroll
    for (int oi = 0; oi < 16; oi++) acc[oi] = b;
    for (int k = 0; k < LATENT; k++) {
        float wv = Wv[k * LATENT + l];
        #pragma unroll
        for (int oi = 0; oi < 16; oi++) acc[oi] += s_hn[oi][k] * wv;
    }
    #pragma unroll
    for (int oi = 0; oi < 16; oi++)
        g_v[(blockIdx.x * 16 + oi) * LATENT + l] = acc[oi];
}

// ---------------- kernel 2: per-query precompute (aq, incl b1) ----------------
__global__ void pre_q_kernel(const float* __restrict__ pos_query,
                             const float* __restrict__ W1,
                             const float* __restrict__ b1) {
    int l = threadIdx.x;
    float aw0 = W1[0 * LATENT + l] + W1[(6 + 0) * LATENT + l];
    float aw1 = W1[1 * LATENT + l] + W1[(6 + 1) * LATENT + l];
    float aw2 = W1[2 * LATENT + l] + W1[(6 + 2) * LATENT + l];
    float bb = b1[l];
    for (int qi = 0; qi < 32; qi++) {
        int q = blockIdx.x * 32 + qi;
        float p0 = pos_query[q * 3 + 0], p1 = pos_query[q * 3 + 1], p2 = pos_query[q * 3 + 2];
        g_aq[q * LATENT + l] = bb + p0 * aw0 + p1 * aw1 + p2 * aw2;
    }
}

// ---------------- kernel 3: fused logits + online softmax + aggregation ----------------
// grid: (N_Q/32, SEGS), 256 threads.
// Warp owns 4 queries in BOTH phases. Phase1: lane = obs. Phase2: lane = 4 latents.
__global__ __launch_bounds__(256, 2) void fused_kernel(
    const float* __restrict__ pos_query, const float* __restrict__ pos_obs,
    const int* __restrict__ query_batch, const int* __restrict__ obs_batch,
    const float* __restrict__ W1, const float* __restrict__ W2) {

    // pool aliases: bo tile (phase1) and w tile (softmax out / phase2 in)
    __shared__ char s_pool[32 * 33 * 16];                 // 16896 B
    __shared__ ulonglong2 s_aq[32][32];                   // [q][lg]
    __shared__ ulonglong2 s_w2[32][4];                    // [lg][h]
    __shared__ ulonglong2 s_wd[32];
    __shared__ float s_pq[32][3];
    __shared__ int s_qb[32];
    __shared__ float s_m[32][4], s_s[32][4], s_f[32][4];

    ulonglong2 (*s_bo)[33] = (ulonglong2(*)[33])s_pool;   // [lg][o]
    float (*s_w)[4][32] = (float(*)[4][32])s_pool;        // [q][h][o] UNPADDED (float4-aligned;
                                                          // phase2 reads are 8-lane broadcasts)

    int t = threadIdx.x;
    int q0 = blockIdx.x * 32;
    int seg = blockIdx.y;
    int ob0 = seg * SEG_O;

    // ---- one-time staging ----
    const float4* aq4 = (const float4*)g_aq;
    for (int i = t; i < 1024; i += 256) {
        int q = i >> 5, lg = i & 31;
        ((float4*)s_aq)[q * 32 + lg] = aq4[(q0 + q) * 32 + lg];
    }
    for (int i = t; i < 512; i += 256) {
        int l = i >> 2, h = i & 3;
        ((float*)s_w2)[(l >> 2) * 16 + h * 4 + (l & 3)] = W2[l * 4 + h];
    }
    if (t < 128) {
        ((float*)s_wd)[t] = W1[9 * LATENT + t];
        int q = t >> 2, h = t & 3;
        s_m[q][h] = -3e38f;
        s_s[q][h] = 0.0f;
    }
    if (t < 32) s_qb[t] = query_batch[q0 + t];
    for (int i = t; i < 96; i += 256) {
        int r = i / 3, p = i % 3;
        s_pq[r][p] = pos_query[(q0 + r) * 3 + p];
    }

    int warp = t >> 5, lane = t & 31;
    int qb4 = warp << 2;
    int h2 = lane >> 3;                 // head for this lane's latent quad (lane*4..+3)

    ull acc2[4][2];
    #pragma unroll
    for (int q = 0; q < 4; q++) { acc2[q][0] = 0ull; acc2[q][1] = 0ull; }

    const float4* bo4 = (const float4*)g_bo;
    const float4* v4p = (const float4*)g_v;

    for (int tile = 0; tile < N_TILES; tile++) {
        int og0 = ob0 + tile * O_TILE;

        __syncthreads();   // prev phase2 done reading pool-as-w
        for (int i = t; i < 1024; i += 256) {
            int o = i >> 5, lg = i & 31;
            *((float4*)&s_bo[lg][o]) = bo4[(og0 + o) * 32 + lg];
        }
        __syncthreads();

        // ---- phase 1: logits ----
        ull d2[4];
        bool ok[4];
        {
            float px = pos_obs[(og0 + lane) * 3 + 0];
            float py = pos_obs[(og0 + lane) * 3 + 1];
            float pz = pos_obs[(og0 + lane) * 3 + 2];
            int obv = obs_batch[og0 + lane];
            #pragma unroll
            for (int q = 0; q < 4; q++) {
                float dx = s_pq[qb4 + q][0] - px;
                float dy = s_pq[qb4 + q][1] - py;
                float dz = s_pq[qb4 + q][2] - pz;
                float dv = __fsqrt_rn(dx * dx + dy * dy + dz * dz);
                d2[q] = pack2(dv, dv);
                ok[q] = (s_qb[qb4 + q] == obv);
            }
        }
        ull acc1[4][4];
        #pragma unroll
        for (int q = 0; q < 4; q++)
            #pragma unroll
            for (int h = 0; h < 4; h++) acc1[q][h] = 0ull;

        #pragma unroll 4
        for (int lg = 0; lg < 32; lg++) {
            ulonglong2 bo = s_bo[lg][lane];
            ulonglong2 wd = s_wd[lg];
            ulonglong2 w0 = s_w2[lg][0], w1 = s_w2[lg][1], w2v = s_w2[lg][2], w3 = s_w2[lg][3];
            #pragma unroll
            for (int q = 0; q < 4; q++) {
                ulonglong2 aq = s_aq[qb4 + q][lg];
                ull ta = relu2(fma2(wd.x, d2[q], add2(aq.x, bo.x)));
                ull tb = relu2(fma2(wd.y, d2[q], add2(aq.y, bo.y)));
                acc1[q][0] = fma2(ta, w0.x, acc1[q][0]);
                acc1[q][1] = fma2(ta, w1.x, acc1[q][1]);
                acc1[q][2] = fma2(ta, w2v.x, acc1[q][2]);
                acc1[q][3] = fma2(ta, w3.x, acc1[q][3]);
                acc1[q][0] = fma2(tb, w0.y, acc1[q][0]);
                acc1[q][1] = fma2(tb, w1.y, acc1[q][1]);
                acc1[q][2] = fma2(tb, w2v.y, acc1[q][2]);
                acc1[q][3] = fma2(tb, w3.y, acc1[q][3]);
            }
        }

        __syncthreads();   // all warps done reading pool-as-bo

        // ---- softmax (writes s_w into pool) ----
        #pragma unroll
        for (int q = 0; q < 4; q++) {
            #pragma unroll
            for (int h = 0; h < 4; h++) {
                float2 a = unpack2(acc1[q][h]);
                float r = ok[q] ? (a.x + a.y) : -1e30f;   // b2 cancels in softmax
                float tm = r;
                #pragma unroll
                for (int off = 16; off; off >>= 1)
                    tm = fmaxf(tm, __shfl_xor_sync(0xffffffffu, tm, off));
                float mo = s_m[qb4 + q][h];               // LDS broadcast
                float mn = fmaxf(mo, tm);
                float wv = __expf(r - mn);
                float sv = wv;
                #pragma unroll
                for (int off = 16; off; off >>= 1)
                    sv += __shfl_xor_sync(0xffffffffu, sv, off);
                s_w[qb4 + q][h][lane] = wv;
                if (lane == 0) {
                    float f = __expf(mo - mn);
                    s_f[qb4 + q][h] = f;
                    s_s[qb4 + q][h] = s_s[qb4 + q][h] * f + sv;
                    s_m[qb4 + q][h] = mn;
                }
            }
        }
        __syncwarp();

        // ---- phase 2: rescale + weighted accumulation (intra-warp) ----
        #pragma unroll
        for (int q = 0; q < 4; q++) {
            float f = s_f[qb4 + q][h2];
            ull fp = pack2(f, f);
            acc2[q][0] = mul2(acc2[q][0], fp);
            acc2[q][1] = mul2(acc2[q][1], fp);
        }
        #pragma unroll
        for (int o4 = 0; o4 < 8; o4++) {
            float4 wq[4];
            #pragma unroll
            for (int q = 0; q < 4; q++)
                wq[q] = *(const float4*)&s_w[qb4 + q][h2][o4 * 4];
            #pragma unroll
            for (int j = 0; j < 4; j++) {
                int o = o4 * 4 + j;
                float4 v4 = __ldg(&v4p[(og0 + o) * 32 + lane]);
                ull v01 = pack2(v4.x, v4.y), v23 = pack2(v4.z, v4.w);
                #pragma unroll
                for (int q = 0; q < 4; q++) {
                    float wsc = (j == 0) ? wq[q].x : (j == 1) ? wq[q].y : (j == 2) ? wq[q].z : wq[q].w;
                    ull wp = pack2(wsc, wsc);
                    acc2[q][0] = fma2(wp, v01, acc2[q][0]);
                    acc2[q][1] = fma2(wp, v23, acc2[q][1]);
                }
            }
        }
    }

    __syncwarp();
    // ---- write per-segment partials ----
    if (lane < 16) {
        int q = lane >> 2, h = lane & 3;
        int qg = q0 + qb4 + q;
        g_m2[(seg * N_Q + qg) * HEADS + h] = s_m[qb4 + q][h];
        g_s2[(seg * N_Q + qg) * HEADS + h] = s_s[qb4 + q][h];
    }
    float4* acc4 = (float4*)g_acc;
    #pragma unroll
    for (int q = 0; q < 4; q++) {
        int qg = q0 + qb4 + q;
        float2 a0 = unpack2(acc2[q][0]);
        float2 a1 = unpack2(acc2[q][1]);
        float4 r; r.x = a0.x; r.y = a0.y; r.z = a1.x; r.w = a1.y;
        acc4[(size_t)(seg * N_Q + qg) * 32 + lane] = r;
    }
}

// ---------------- kernel 4: combine segment partials ----------------
// thread = (q, latent-quad): N_Q*32 threads
__global__ void combine_kernel(float* __restrict__ out) {
    int idx = blockIdx.x * 256 + threadIdx.x;
    int q = idx >> 5, lq = idx & 31, h = lq >> 3;
    const float4* acc4 = (const float4*)g_acc;
    float ms[SEGS];
    float M = -3e38f;
    #pragma unroll
    for (int s = 0; s < SEGS; s++) {
        ms[s] = g_m2[(s * N_Q + q) * HEADS + h];
        M = fmaxf(M, ms[s]);
    }
    float S = 0.0f;
    float4 A; A.x = A.y = A.z = A.w = 0.0f;
    #pragma unroll
    for (int s = 0; s < SEGS; s++) {
        float e = __expf(ms[s] - M);
        S += g_s2[(s * N_Q + q) * HEADS + h] * e;
        float4 a = acc4[(size_t)(s * N_Q + q) * 32 + lq];
        A.x += a.x * e; A.y += a.y * e; A.z += a.z * e; A.w += a.w * e;
    }
    float inv = 1.0f / S;
    float4 r; r.x = A.x * inv; r.y = A.y * inv; r.z = A.z * inv; r.w = A.w * inv;
    ((float4*)out)[idx] = r;
}

// ---------------- launch ----------------
extern "C" void kernel_launch(void* const* d_in, const int* in_sizes, int n_in,
                              void* d_out, int out_size) {
    const float* h_obs      = (const float*)d_in[0];
    const float* pos_obs    = (const float*)d_in[1];
    const float* pos_query  = (const float*)d_in[2];
    const int*   obs_batch  = (const int*)d_in[3];
    const int*   query_batch= (const int*)d_in[4];
    const float* W1         = (const float*)d_in[5];
    const float* b1         = (const float*)d_in[6];
    const float* W2         = (const float*)d_in[7];
    const float* ln_gamma   = (const float*)d_in[9];
    const float* ln_beta    = (const float*)d_in[10];
    const float* Wv         = (const float*)d_in[11];
    const float* bv         = (const float*)d_in[12];
    float* out = (float*)d_out;

    pre_o_kernel<<<N_O / 16, 128>>>(h_obs, pos_obs, W1, ln_gamma, ln_beta, Wv, bv);
    pre_q_kernel<<<N_Q / 32, 128>>>(pos_query, W1, b1);
    fused_kernel<<<dim3(N_Q / 32, SEGS), 256>>>(pos_query, pos_obs, query_batch, obs_batch, W1, W2);
    combine_kernel<<<(N_Q * 32) / 256, 256>>>(out);
}